// round 4
// baseline (speedup 1.0000x reference)
#include <cuda_runtime.h>
#include <cuda.h>
#include <cstdint>
#include <math.h>

// ============================ problem constants ============================
#define L_DIM  1024
#define B_DIM  8
#define CIN    1024
#define COUT   1024
#define KEXP   4
#define CCOND  256
#define HIDD   64

// ============================ GEMM tiling ============================
#define TM   128            // M tile (L dimension)
#define TN   256            // N tile (C_OUT dimension)
#define KC   32             // K floats per stage (128B row = SW128 atom)
#define NKC  (CIN / KC)     // 32 K-chunks
#define NS   4              // pipeline stages
#define NWARP_C 8           // compute warps
#define NTHREADS (NWARP_C * 32 + 32)   // + 1 producer warp = 288

#define A_STAGE_BYTES (TM * KC * 4)          // 16384
#define B_STAGE_BYTES (TN * KC * 4)          // 32768
#define STAGE_BYTES   (A_STAGE_BYTES + B_STAGE_BYTES)

#define OFF_FULL   0u
#define OFF_EMPTY  (8u * NS)
#define OFF_A      1024u
#define OFF_B      (1024u + NS * A_STAGE_BYTES)                // 66560
#define SMEM_TOTAL ((int)(OFF_B + NS * B_STAGE_BYTES))         // 197632

// ============================ scratch (device globals; no allocs) ============================
__device__ __align__(256) float g_w[(size_t)B_DIM * COUT * CIN];   // 32 MB aggregated + tf32-RNA weights
__device__ __align__(16)  float g_bb[B_DIM * COUT];                // aggregated bias
__device__ __align__(16)  float g_att[B_DIM * KEXP];               // softmax attention

// ============================ PTX helpers (sm_100 BASELINE only) ============================
__device__ __forceinline__ uint32_t smem_u32(const void* p) {
    uint32_t a;
    asm("{ .reg .u64 t; cvta.to.shared.u64 t, %1; cvt.u32.u64 %0, t; }" : "=r"(a) : "l"(p));
    return a;
}

#define MBARRIER_INIT(addr, cnt) \
    asm volatile("mbarrier.init.shared.b64 [%0], %1;" :: "r"(addr), "r"((uint32_t)(cnt)) : "memory")

#define MBARRIER_EXPECT_TX(addr, bytes) \
    asm volatile("mbarrier.arrive.expect_tx.shared.b64 _, [%0], %1;" :: "r"(addr), "r"((uint32_t)(bytes)) : "memory")

#define MBARRIER_ARRIVE(addr) \
    asm volatile("mbarrier.arrive.shared.b64 _, [%0];" :: "r"(addr) : "memory")

#define MBAR_INVAL(addr) \
    asm volatile("mbarrier.inval.shared.b64 [%0];" :: "r"(addr) : "memory")

#define MBARRIER_WAIT_PARITY(mbar_smem_addr, phase_parity) do {                          \
    uint32_t _mbar = (uint32_t)(mbar_smem_addr);                                         \
    uint32_t _parity = (uint32_t)(phase_parity);                                         \
    uint32_t _done;                                                                      \
    asm volatile(                                                                        \
        "{\n\t"                                                                          \
        ".reg .pred p;\n\t"                                                              \
        "mbarrier.try_wait.parity.acquire.cta.shared::cta.b64 p, [%1], %2;\n\t"          \
        "selp.b32 %0, 1, 0, p;\n\t"                                                      \
        "}"                                                                              \
        : "=r"(_done) : "r"(_mbar), "r"(_parity) : "memory");                            \
    if (!_done) {                                                                        \
        asm volatile(                                                                    \
            "{\n\t"                                                                      \
            ".reg .pred P1;\n\t"                                                         \
            "WAIT_LOOP_%=:\n\t"                                                          \
            "mbarrier.try_wait.parity.acquire.cta.shared::cta.b64 P1, [%0], %1, 0x989680;\n\t" \
            "@P1 bra.uni WAIT_DONE_%=;\n\t"                                              \
            "bra.uni WAIT_LOOP_%=;\n\t"                                                  \
            "WAIT_DONE_%=:\n\t"                                                          \
            "}"                                                                          \
            :: "r"(_mbar), "r"(_parity) : "memory");                                     \
    }                                                                                    \
} while (0)

#define TMA_LOAD_3D(smem_addr, tensor_map, cx, cy, cz, mbar) \
    asm volatile( \
        "cp.async.bulk.tensor.3d.shared::cta.global.tile.mbarrier::complete_tx::bytes " \
        "[%0], [%1, {%2, %3, %4}], [%5];" \
        :: "r"((uint32_t)(smem_addr)), "l"(tensor_map), \
           "r"((int32_t)(cx)), "r"((int32_t)(cy)), "r"((int32_t)(cz)), \
           "r"((uint32_t)(mbar)) \
        : "memory")

#define FENCE_PROXY() \
    asm volatile("fence.proxy.async.shared::cta;" ::: "memory")

__device__ __forceinline__ uint32_t lds_u32(uint32_t addr) {
    uint32_t v;
    asm volatile("ld.shared.b32 %0, [%1];" : "=r"(v) : "r"(addr));
    return v;
}

// tf32 round-to-nearest (ties away): add half-ulp at bit 13, mask. Carry into
// the exponent is correct rounding. Inputs are finite, so no NaN/Inf handling.
__device__ __forceinline__ uint32_t tf32_rna_u32(uint32_t u) {
    return (u + 0x1000u) & 0xFFFFE000u;
}
__device__ __forceinline__ float tf32_round(float v) {
    return __uint_as_float(tf32_rna_u32(__float_as_uint(v)));
}

// mma.sync m16n8k8 tf32 (sm_80+ baseline)
__device__ __forceinline__ void mma_tf32(float* d, const uint32_t* a, const uint32_t* b) {
    asm volatile(
        "mma.sync.aligned.m16n8k8.row.col.f32.tf32.tf32.f32 "
        "{%0,%1,%2,%3}, {%4,%5,%6,%7}, {%8,%9}, {%0,%1,%2,%3};"
        : "+f"(d[0]), "+f"(d[1]), "+f"(d[2]), "+f"(d[3])
        : "r"(a[0]), "r"(a[1]), "r"(a[2]), "r"(a[3]), "r"(b[0]), "r"(b[1]));
}

// ============================ kernel 1: attention + aggregated bias ============================
__global__ void attn_kernel(const float* __restrict__ cond,
                            const float* __restrict__ fc1w, const float* __restrict__ fc1b,
                            const float* __restrict__ fc2w, const float* __restrict__ fc2b,
                            const float* __restrict__ bias) {
    __shared__ float h[B_DIM][HIDD];
    __shared__ float lo[B_DIM][KEXP];
    __shared__ float att[B_DIM][KEXP];
    const int t = threadIdx.x;   // 512 threads

    {
        const int b = t >> 6, j = t & 63;
        const float* c = cond + b * CCOND;
        const float* w = fc1w + j * CCOND;
        float acc = fc1b[j];
        #pragma unroll 8
        for (int i = 0; i < CCOND; i++) acc = fmaf(c[i], w[i], acc);
        h[b][j] = fmaxf(acc, 0.0f);
    }
    __syncthreads();

    if (t < B_DIM * KEXP) {
        const int b = t >> 2, k = t & 3;
        const float* w = fc2w + k * HIDD;
        float acc = fc2b[k];
        #pragma unroll 8
        for (int i = 0; i < HIDD; i++) acc = fmaf(h[b][i], w[i], acc);
        lo[b][k] = acc * (1.0f / 30.0f);
    }
    __syncthreads();

    if (t < B_DIM) {
        float m = fmaxf(fmaxf(lo[t][0], lo[t][1]), fmaxf(lo[t][2], lo[t][3]));
        float e[KEXP], s = 0.0f;
        #pragma unroll
        for (int k = 0; k < KEXP; k++) { e[k] = expf(lo[t][k] - m); s += e[k]; }
        float inv = 1.0f / s;
        #pragma unroll
        for (int k = 0; k < KEXP; k++) { att[t][k] = e[k] * inv; g_att[t * KEXP + k] = e[k] * inv; }
    }
    __syncthreads();

    for (int idx = t; idx < B_DIM * COUT; idx += 512) {
        const int b = idx >> 10, o = idx & 1023;
        float acc = 0.0f;
        #pragma unroll
        for (int k = 0; k < KEXP; k++) acc = fmaf(att[b][k], bias[k * COUT + o], acc);
        g_bb[idx] = acc;
    }
}

// ============================ kernel 2: per-sample weight aggregation (+ tf32-RNA round) ============================
__global__ void wagg_kernel(const float* __restrict__ weight) {
    __shared__ float a[B_DIM * KEXP];
    if (threadIdx.x < B_DIM * KEXP) a[threadIdx.x] = g_att[threadIdx.x];
    __syncthreads();

    const int t = blockIdx.x * blockDim.x + threadIdx.x;   // over COUT*CIN/4 float4s
    const float4* w4 = reinterpret_cast<const float4*>(weight);
    float4 wk[KEXP];
    #pragma unroll
    for (int k = 0; k < KEXP; k++) wk[k] = w4[k * (COUT * CIN / 4) + t];

    float4* g4 = reinterpret_cast<float4*>(g_w);
    #pragma unroll
    for (int b = 0; b < B_DIM; b++) {
        float4 acc = make_float4(0.f, 0.f, 0.f, 0.f);
        #pragma unroll
        for (int k = 0; k < KEXP; k++) {
            const float ab = a[b * KEXP + k];
            acc.x = fmaf(ab, wk[k].x, acc.x);
            acc.y = fmaf(ab, wk[k].y, acc.y);
            acc.z = fmaf(ab, wk[k].z, acc.z);
            acc.w = fmaf(ab, wk[k].w, acc.w);
        }
        acc.x = tf32_round(acc.x); acc.y = tf32_round(acc.y);
        acc.z = tf32_round(acc.z); acc.w = tf32_round(acc.w);
        g4[b * (COUT * CIN / 4) + t] = acc;
    }
}

// ============================ kernel 3: tf32 mma.sync batched GEMM ============================
// A (x): TM x KC stages, SW128. B (g_w): TN x KC stages, SW128.
// 8 compute warps (2Mx4N grid, 64x64 warp tile) + warp 8 = TMA producer.
__global__ void __launch_bounds__(NTHREADS, 1)
gemm_tf32_kernel(const __grid_constant__ CUtensorMap tmx,
                 const __grid_constant__ CUtensorMap tmw,
                 const float* __restrict__ bb,
                 float* __restrict__ out,
                 int enabled) {
    if (!enabled) return;     // fallback path active: SIMT kernel does the work
    extern __shared__ char smem[];
    const uint32_t sb = smem_u32(smem);
    const int tid  = threadIdx.x;
    const int wid  = tid >> 5;
    const int lane = tid & 31;
    const int g = lane >> 2;      // group id (0..7)
    const int t = lane & 3;       // thread-in-group (0..3)
    const int l0 = blockIdx.x * TM;
    const int o0 = blockIdx.y * TN;
    const int b  = blockIdx.z;

    if (tid == 0) {
        #pragma unroll
        for (int s = 0; s < NS; s++) {
            MBARRIER_INIT(sb + OFF_FULL + 8 * s, 1);        // tx-based
            MBARRIER_INIT(sb + OFF_EMPTY + 8 * s, NWARP_C); // 1 arrive per compute warp
        }
        FENCE_PROXY();
    }
    __syncthreads();

    if (wid == NWARP_C) {
        // ---------------- producer warp ----------------
        if (lane == 0) {
            int ps = 0, pp = 1;
            #pragma unroll 1
            for (int kc = 0; kc < NKC; kc++) {
                MBARRIER_WAIT_PARITY(sb + OFF_EMPTY + 8 * ps, pp);
                MBARRIER_EXPECT_TX(sb + OFF_FULL + 8 * ps, STAGE_BYTES);
                TMA_LOAD_3D(sb + OFF_A + ps * A_STAGE_BYTES, &tmx, kc * KC, b, l0, sb + OFF_FULL + 8 * ps);
                TMA_LOAD_3D(sb + OFF_B + ps * B_STAGE_BYTES, &tmw, kc * KC, o0, b, sb + OFF_FULL + 8 * ps);
                if (++ps == NS) { ps = 0; pp ^= 1; }
            }
        }
    } else {
        // ---------------- compute warps ----------------
        const int wm = wid & 1;        // 0..1 -> M offset
        const int wn = wid >> 1;       // 0..3 -> N offset
        const uint32_t rowA0 = (uint32_t)(wm * 64 + g) * 128;      // + i*2048 (+1024 for +8 rows)
        const uint32_t rowB0 = (uint32_t)(wn * 64 + g) * 128;      // + j*1024

        float acc[4][8][4];
        #pragma unroll
        for (int i = 0; i < 4; i++)
            #pragma unroll
            for (int j = 0; j < 8; j++)
                #pragma unroll
                for (int q = 0; q < 4; q++) acc[i][j][q] = 0.0f;

        int cs = 0, cp = 0;
        #pragma unroll 1
        for (int kc = 0; kc < NKC; kc++) {
            MBARRIER_WAIT_PARITY(sb + OFF_FULL + 8 * cs, cp);
            const uint32_t sA = sb + OFF_A + cs * A_STAGE_BYTES + rowA0;
            const uint32_t sB = sb + OFF_B + cs * B_STAGE_BYTES + rowB0;

            #pragma unroll
            for (int s = 0; s < 4; s++) {
                // SW128: byte col for chunk (2s) is 16*((2s)^g)+4t; next chunk flips bit4
                const uint32_t c0 = ((((uint32_t)(2 * s) ^ (uint32_t)g) << 4) | ((uint32_t)t << 2));
                const uint32_t c1 = c0 ^ 16u;

                uint32_t afr[4][4];
                #pragma unroll
                for (int i = 0; i < 4; i++) {
                    const uint32_t r0 = sA + (uint32_t)i * 2048u;
                    afr[i][0] = tf32_rna_u32(lds_u32(r0 + c0));          // row g,   col t
                    afr[i][1] = tf32_rna_u32(lds_u32(r0 + 1024u + c0));  // row g+8, col t
                    afr[i][2] = tf32_rna_u32(lds_u32(r0 + c1));          // row g,   col t+4
                    afr[i][3] = tf32_rna_u32(lds_u32(r0 + 1024u + c1));  // row g+8, col t+4
                }
                uint32_t bfr[8][2];
                #pragma unroll
                for (int j = 0; j < 8; j++) {
                    const uint32_t rb = sB + (uint32_t)j * 1024u;
                    bfr[j][0] = lds_u32(rb + c0);   // k=t,   n=g   (pre-rounded in wagg)
                    bfr[j][1] = lds_u32(rb + c1);   // k=t+4, n=g
                }
                #pragma unroll
                for (int i = 0; i < 4; i++)
                    #pragma unroll
                    for (int j = 0; j < 8; j++)
                        mma_tf32(acc[i][j], afr[i], bfr[j]);
            }

            __syncwarp();
            if (lane == 0) MBARRIER_ARRIVE(sb + OFF_EMPTY + 8 * cs);
            if (++cs == NS) { cs = 0; cp ^= 1; }
        }

        // ---------------- epilogue: registers -> gmem with bias ----------------
        const int colbase = o0 + wn * 64 + 2 * t;
        float2 bv[8];
        #pragma unroll
        for (int j = 0; j < 8; j++)
            bv[j] = *reinterpret_cast<const float2*>(bb + b * COUT + colbase + j * 8);

        #pragma unroll
        for (int i = 0; i < 4; i++) {
            #pragma unroll
            for (int p = 0; p < 2; p++) {
                const int l = l0 + wm * 64 + i * 16 + g + 8 * p;
                float* orow = out + ((size_t)l * B_DIM + b) * COUT + colbase;
                #pragma unroll
                for (int j = 0; j < 8; j++) {
                    float2 v;
                    v.x = acc[i][j][2 * p]     + bv[j].x;
                    v.y = acc[i][j][2 * p + 1] + bv[j].y;
                    *reinterpret_cast<float2*>(orow + j * 8) = v;
                }
            }
        }
    }

    __syncthreads();
    if (tid == 0) {
        #pragma unroll
        for (int s = 0; s < NS; s++) {
            MBAR_INVAL(sb + OFF_FULL + 8 * s);
            MBAR_INVAL(sb + OFF_EMPTY + 8 * s);
        }
    }
}

// ============================ fallback: SIMT fp32 GEMM (no TMA/tensor maps) ============================
// Only used if tensor-map encoding is unavailable; guaranteed to terminate.
// One block = 64 L-rows x 128 cols for one b. Plain smem tiling.
__global__ void __launch_bounds__(256, 2)
gemm_fallback_kernel(const float* __restrict__ x, const float* __restrict__ bb,
                     float* __restrict__ out, int enabled) {
    if (!enabled) return;
    __shared__ float sx[64][33];     // 64 rows x 32 k (padded)
    const int l0 = blockIdx.x * 64;
    const int o0 = blockIdx.y * 128;
    const int b  = blockIdx.z;
    const int tid = threadIdx.x;
    const int tr = tid >> 5;         // 0..7 row group
    const int tc = tid & 31;

    float acc[8][4];                 // each thread: 8 rows (stride 8) x 4 cols (stride 32)
    #pragma unroll
    for (int i = 0; i < 8; i++)
        #pragma unroll
        for (int j = 0; j < 4; j++) acc[i][j] = 0.0f;

    for (int k0 = 0; k0 < CIN; k0 += 32) {
        __syncthreads();
        #pragma unroll
        for (int i = 0; i < 8; i++) {
            const int row = tr + i * 8;
            sx[row][tc] = x[((size_t)(l0 + row) * B_DIM + b) * CIN + k0 + tc];
        }
        __syncthreads();
        #pragma unroll 4
        for (int kk = 0; kk < 32; kk++) {
            float wv[4];
            #pragma unroll
            for (int j = 0; j < 4; j++)
                wv[j] = g_w[((size_t)b * COUT + o0 + tc + 32 * j) * CIN + k0 + kk];
            #pragma unroll
            for (int i = 0; i < 8; i++) {
                const float xv = sx[tr + i * 8][kk];
                #pragma unroll
                for (int j = 0; j < 4; j++) acc[i][j] = fmaf(xv, wv[j], acc[i][j]);
            }
        }
    }
    #pragma unroll
    for (int i = 0; i < 8; i++) {
        const int l = l0 + tr + i * 8;
        #pragma unroll
        for (int j = 0; j < 4; j++) {
            const int o = o0 + tc + 32 * j;
            out[((size_t)l * B_DIM + b) * COUT + o] = acc[i][j] + bb[b * COUT + o];
        }
    }
}

// ============================ host launch ============================
typedef CUresult (CUDAAPI *EncodeTiledFn)(
    CUtensorMap*, CUtensorMapDataType, cuuint32_t, void*,
    const cuuint64_t*, const cuuint64_t*, const cuuint32_t*, const cuuint32_t*,
    CUtensorMapInterleave, CUtensorMapSwizzle, CUtensorMapL2promotion, CUtensorMapFloatOOBfill);

extern "C" void kernel_launch(void* const* d_in, const int* in_sizes, int n_in,
                              void* d_out, int out_size) {
    const float* x      = (const float*)d_in[0];
    const float* cond   = (const float*)d_in[1];
    const float* fc1w   = (const float*)d_in[2];
    const float* fc1b   = (const float*)d_in[3];
    const float* fc2w   = (const float*)d_in[4];
    const float* fc2b   = (const float*)d_in[5];
    const float* weight = (const float*)d_in[6];
    const float* bias   = (const float*)d_in[7];
    float* out = (float*)d_out;

    void *p_w = nullptr, *p_bb = nullptr;
    cudaGetSymbolAddress(&p_w, g_w);
    cudaGetSymbolAddress(&p_bb, g_bb);

    // Resolve cuTensorMapEncodeTiled defensively; fall back to SIMT path on ANY failure.
    EncodeTiledFn enc = nullptr;
    {
        cudaDriverEntryPointQueryResult qres = cudaDriverEntryPointSymbolNotFound;
        cudaError_t e = cudaGetDriverEntryPointByVersion(
            "cuTensorMapEncodeTiled", (void**)&enc, 12000, cudaEnableDefault, &qres);
        if (e != cudaSuccess || qres != cudaDriverEntryPointSuccess) enc = nullptr;
        if (!enc) {
            qres = cudaDriverEntryPointSymbolNotFound;
            e = cudaGetDriverEntryPoint("cuTensorMapEncodeTiled", (void**)&enc,
                                        cudaEnableDefault, &qres);
            if (e != cudaSuccess || qres != cudaDriverEntryPointSuccess) enc = nullptr;
        }
    }

    CUtensorMap tmx, tmw;
    bool fast = (enc != nullptr);
    if (fast) {
        // x: logical dims (CIN, B, L), box (KC, 1, TM), SW128
        cuuint64_t dimsx[3]    = {CIN, B_DIM, L_DIM};
        cuuint64_t stridesx[2] = {(cuuint64_t)CIN * 4, (cuuint64_t)CIN * B_DIM * 4};
        cuuint32_t boxx[3]     = {KC, 1, TM};
        cuuint32_t es[3]       = {1, 1, 1};
        if (enc(&tmx, CU_TENSOR_MAP_DATA_TYPE_FLOAT32, 3, (void*)x, dimsx, stridesx, boxx, es,
                CU_TENSOR_MAP_INTERLEAVE_NONE, CU_TENSOR_MAP_SWIZZLE_128B,
                CU_TENSOR_MAP_L2_PROMOTION_L2_128B, CU_TENSOR_MAP_FLOAT_OOB_FILL_NONE)
            != CUDA_SUCCESS) fast = false;
        // w_agg: logical dims (CIN, COUT, B), box (KC, TN, 1), SW128
        cuuint64_t dimsw[3]    = {CIN, COUT, B_DIM};
        cuuint64_t stridesw[2] = {(cuuint64_t)CIN * 4, (cuuint64_t)CIN * COUT * 4};
        cuuint32_t boxw[3]     = {KC, TN, 1};
        if (fast &&
            enc(&tmw, CU_TENSOR_MAP_DATA_TYPE_FLOAT32, 3, p_w, dimsw, stridesw, boxw, es,
                CU_TENSOR_MAP_INTERLEAVE_NONE, CU_TENSOR_MAP_SWIZZLE_128B,
                CU_TENSOR_MAP_L2_PROMOTION_L2_128B, CU_TENSOR_MAP_FLOAT_OOB_FILL_NONE)
            != CUDA_SUCCESS) fast = false;
    }
    if (!fast) {
        // dummy (valid-zero) maps so the kernel argument is well-formed; kernel is disabled.
        memset(&tmx, 0, sizeof(tmx));
        memset(&tmw, 0, sizeof(tmw));
    }

    attn_kernel<<<1, 512>>>(cond, fc1w, fc1b, fc2w, fc2b, bias);
    wagg_kernel<<<(COUT * CIN / 4) / 256, 256>>>(weight);

    if (fast) {
        cudaFuncSetAttribute(gemm_tf32_kernel, cudaFuncAttributeMaxDynamicSharedMemorySize, SMEM_TOTAL);
        gemm_tf32_kernel<<<dim3(L_DIM / TM, COUT / TN, B_DIM), NTHREADS, SMEM_TOTAL>>>(
            tmx, tmw, (const float*)p_bb, out, 1);
    } else {
        gemm_fallback_kernel<<<dim3(L_DIM / 64, COUT / 128, B_DIM), 256>>>(
            x, (const float*)p_bb, out, 1);
    }
}

// round 5
// speedup vs baseline: 1.3458x; 1.3458x over previous
#include <cuda_runtime.h>
#include <cuda.h>
#include <cstdint>
#include <math.h>

// ============================ problem constants ============================
#define L_DIM  1024
#define B_DIM  8
#define CIN    1024
#define COUT   1024
#define KEXP   4
#define CCOND  256
#define HIDD   64

// ============================ GEMM tiling ============================
#define TM   128            // M tile (L dimension)
#define TN   256            // N tile (C_OUT dimension)
#define KC   32             // K floats per stage (128B row = SW128 atom)
#define NKC  (CIN / KC)     // 32 K-chunks
#define NS   4              // pipeline stages
#define NWARP_C 8           // compute warps
#define NTHREADS (NWARP_C * 32 + 32)   // + 1 producer warp = 288

#define A_STAGE_BYTES (TM * KC * 4)          // 16384
#define B_STAGE_BYTES (TN * KC * 4)          // 32768
#define STAGE_BYTES   (A_STAGE_BYTES + B_STAGE_BYTES)

#define OFF_FULL   0u
#define OFF_EMPTY  (8u * NS)
#define OFF_A      1024u
#define OFF_B      (1024u + NS * A_STAGE_BYTES)                // 66560
#define SMEM_TOTAL ((int)(OFF_B + NS * B_STAGE_BYTES))         // 197632

// ============================ scratch (device globals; no allocs) ============================
__device__ __align__(256) float g_w[(size_t)B_DIM * COUT * CIN];   // 32 MB aggregated + tf32-RNA weights
__device__ __align__(16)  float g_bb[B_DIM * COUT];                // aggregated bias
__device__ __align__(16)  float g_att[B_DIM * KEXP];               // softmax attention

// ============================ PTX helpers (sm_100 BASELINE only) ============================
__device__ __forceinline__ uint32_t smem_u32(const void* p) {
    uint32_t a;
    asm("{ .reg .u64 t; cvta.to.shared.u64 t, %1; cvt.u32.u64 %0, t; }" : "=r"(a) : "l"(p));
    return a;
}

#define MBARRIER_INIT(addr, cnt) \
    asm volatile("mbarrier.init.shared.b64 [%0], %1;" :: "r"(addr), "r"((uint32_t)(cnt)) : "memory")

#define MBARRIER_EXPECT_TX(addr, bytes) \
    asm volatile("mbarrier.arrive.expect_tx.shared.b64 _, [%0], %1;" :: "r"(addr), "r"((uint32_t)(bytes)) : "memory")

#define MBARRIER_ARRIVE(addr) \
    asm volatile("mbarrier.arrive.shared.b64 _, [%0];" :: "r"(addr) : "memory")

#define MBAR_INVAL(addr) \
    asm volatile("mbarrier.inval.shared.b64 [%0];" :: "r"(addr) : "memory")

#define MBARRIER_WAIT_PARITY(mbar_smem_addr, phase_parity) do {                          \
    uint32_t _mbar = (uint32_t)(mbar_smem_addr);                                         \
    uint32_t _parity = (uint32_t)(phase_parity);                                         \
    uint32_t _done;                                                                      \
    asm volatile(                                                                        \
        "{\n\t"                                                                          \
        ".reg .pred p;\n\t"                                                              \
        "mbarrier.try_wait.parity.acquire.cta.shared::cta.b64 p, [%1], %2;\n\t"          \
        "selp.b32 %0, 1, 0, p;\n\t"                                                      \
        "}"                                                                              \
        : "=r"(_done) : "r"(_mbar), "r"(_parity) : "memory");                            \
    if (!_done) {                                                                        \
        asm volatile(                                                                    \
            "{\n\t"                                                                      \
            ".reg .pred P1;\n\t"                                                         \
            "WAIT_LOOP_%=:\n\t"                                                          \
            "mbarrier.try_wait.parity.acquire.cta.shared::cta.b64 P1, [%0], %1, 0x989680;\n\t" \
            "@P1 bra.uni WAIT_DONE_%=;\n\t"                                              \
            "bra.uni WAIT_LOOP_%=;\n\t"                                                  \
            "WAIT_DONE_%=:\n\t"                                                          \
            "}"                                                                          \
            :: "r"(_mbar), "r"(_parity) : "memory");                                     \
    }                                                                                    \
} while (0)

#define TMA_LOAD_3D(smem_addr, tensor_map, cx, cy, cz, mbar) \
    asm volatile( \
        "cp.async.bulk.tensor.3d.shared::cta.global.tile.mbarrier::complete_tx::bytes " \
        "[%0], [%1, {%2, %3, %4}], [%5];" \
        :: "r"((uint32_t)(smem_addr)), "l"(tensor_map), \
           "r"((int32_t)(cx)), "r"((int32_t)(cy)), "r"((int32_t)(cz)), \
           "r"((uint32_t)(mbar)) \
        : "memory")

#define FENCE_PROXY() \
    asm volatile("fence.proxy.async.shared::cta;" ::: "memory")

__device__ __forceinline__ uint32_t lds_u32(uint32_t addr) {
    uint32_t v;
    asm volatile("ld.shared.b32 %0, [%1];" : "=r"(v) : "r"(addr));
    return v;
}

// tf32 round-to-nearest (ties away): add half-ulp at bit 13, mask. Carry into
// the exponent is correct rounding. Inputs are finite, so no NaN/Inf handling.
__device__ __forceinline__ uint32_t tf32_rna_u32(uint32_t u) {
    return (u + 0x1000u) & 0xFFFFE000u;
}
__device__ __forceinline__ float tf32_round(float v) {
    return __uint_as_float(tf32_rna_u32(__float_as_uint(v)));
}

// mma.sync m16n8k8 tf32 (sm_80+ baseline)
__device__ __forceinline__ void mma_tf32(float* d, const uint32_t* a, const uint32_t* b) {
    asm volatile(
        "mma.sync.aligned.m16n8k8.row.col.f32.tf32.tf32.f32 "
        "{%0,%1,%2,%3}, {%4,%5,%6,%7}, {%8,%9}, {%0,%1,%2,%3};"
        : "+f"(d[0]), "+f"(d[1]), "+f"(d[2]), "+f"(d[3])
        : "r"(a[0]), "r"(a[1]), "r"(a[2]), "r"(a[3]), "r"(b[0]), "r"(b[1]));
}

// ============================ kernel 1: attention + aggregated bias ============================
// Phase 1 rewritten: warp-cooperative dot products with coalesced fc1w reads.
__global__ void attn_kernel(const float* __restrict__ cond,
                            const float* __restrict__ fc1w, const float* __restrict__ fc1b,
                            const float* __restrict__ fc2w, const float* __restrict__ fc2b,
                            const float* __restrict__ bias) {
    __shared__ float sc[B_DIM][CCOND];     // staged cond (8 KB)
    __shared__ float h[B_DIM][HIDD];
    __shared__ float lo[B_DIM][KEXP];
    __shared__ float att[B_DIM][KEXP];
    const int t = threadIdx.x;   // 512 threads
    const int w = t >> 5, l = t & 31;

    // stage cond coalesced: 2048 floats / 512 threads
    #pragma unroll
    for (int i = t; i < B_DIM * CCOND; i += 512)
        (&sc[0][0])[i] = cond[i];
    __syncthreads();

    // h = relu(cond @ fc1_w^T + fc1_b): 512 outputs, 32 per warp, warp-reduced.
    // Lane reads fc1w[j*256 + l + 32*i] -> 128B coalesced lines.
    #pragma unroll 1
    for (int r = 0; r < 32; r++) {
        const int idx = w * 32 + r;            // 0..511
        const int b = idx >> 6, j = idx & 63;
        const float* fw = fc1w + j * CCOND;
        float s = 0.0f;
        #pragma unroll
        for (int i = 0; i < CCOND / 32; i++)   // 8 coalesced loads, MLP 8
            s = fmaf(sc[b][l + 32 * i], fw[l + 32 * i], s);
        #pragma unroll
        for (int o = 16; o; o >>= 1) s += __shfl_xor_sync(0xFFFFFFFFu, s, o);
        if (l == 0) h[b][j] = fmaxf(s + fc1b[j], 0.0f);
    }
    __syncthreads();

    // logits = (h @ fc2_w^T + fc2_b) / TEMP   (8 x 4)
    if (t < B_DIM * KEXP) {
        const int b = t >> 2, k = t & 3;
        const float* wv = fc2w + k * HIDD;
        float acc = fc2b[k];
        #pragma unroll 8
        for (int i = 0; i < HIDD; i++) acc = fmaf(h[b][i], wv[i], acc);
        lo[b][k] = acc * (1.0f / 30.0f);
    }
    __syncthreads();

    // softmax over K=4
    if (t < B_DIM) {
        float m = fmaxf(fmaxf(lo[t][0], lo[t][1]), fmaxf(lo[t][2], lo[t][3]));
        float e[KEXP], s = 0.0f;
        #pragma unroll
        for (int k = 0; k < KEXP; k++) { e[k] = expf(lo[t][k] - m); s += e[k]; }
        float inv = 1.0f / s;
        #pragma unroll
        for (int k = 0; k < KEXP; k++) { att[t][k] = e[k] * inv; g_att[t * KEXP + k] = e[k] * inv; }
    }
    __syncthreads();

    // b_b = att @ bias   (8 x 1024), coalesced over o
    for (int idx = t; idx < B_DIM * COUT; idx += 512) {
        const int b = idx >> 10, o = idx & 1023;
        float acc = 0.0f;
        #pragma unroll
        for (int k = 0; k < KEXP; k++) acc = fmaf(att[b][k], bias[k * COUT + o], acc);
        g_bb[idx] = acc;
    }
}

// ============================ kernel 2: per-sample weight aggregation (+ tf32-RNA round) ============================
__global__ void wagg_kernel(const float* __restrict__ weight) {
    __shared__ float a[B_DIM * KEXP];
    if (threadIdx.x < B_DIM * KEXP) a[threadIdx.x] = g_att[threadIdx.x];
    __syncthreads();

    const int t = blockIdx.x * blockDim.x + threadIdx.x;   // over COUT*CIN/4 float4s
    const float4* w4 = reinterpret_cast<const float4*>(weight);
    float4 wk[KEXP];
    #pragma unroll
    for (int k = 0; k < KEXP; k++) wk[k] = w4[k * (COUT * CIN / 4) + t];

    float4* g4 = reinterpret_cast<float4*>(g_w);
    #pragma unroll
    for (int b = 0; b < B_DIM; b++) {
        float4 acc = make_float4(0.f, 0.f, 0.f, 0.f);
        #pragma unroll
        for (int k = 0; k < KEXP; k++) {
            const float ab = a[b * KEXP + k];
            acc.x = fmaf(ab, wk[k].x, acc.x);
            acc.y = fmaf(ab, wk[k].y, acc.y);
            acc.z = fmaf(ab, wk[k].z, acc.z);
            acc.w = fmaf(ab, wk[k].w, acc.w);
        }
        acc.x = tf32_round(acc.x); acc.y = tf32_round(acc.y);
        acc.z = tf32_round(acc.z); acc.w = tf32_round(acc.w);
        g4[b * (COUT * CIN / 4) + t] = acc;
    }
}

// ============================ kernel 3: tf32 mma.sync batched GEMM ============================
// A (x): TM x KC stages, SW128. B (g_w): TN x KC stages, SW128.
// 8 compute warps (2Mx4N grid, 64x64 warp tile) + warp 8 = TMA producer.
__global__ void __launch_bounds__(NTHREADS, 1)
gemm_tf32_kernel(const __grid_constant__ CUtensorMap tmx,
                 const __grid_constant__ CUtensorMap tmw,
                 const float* __restrict__ bb,
                 float* __restrict__ out,
                 int enabled) {
    if (!enabled) return;     // fallback path active: SIMT kernel does the work
    extern __shared__ char smem[];
    const uint32_t sb = smem_u32(smem);
    const int tid  = threadIdx.x;
    const int wid  = tid >> 5;
    const int lane = tid & 31;
    const int g = lane >> 2;      // group id (0..7)
    const int t = lane & 3;       // thread-in-group (0..3)
    const int l0 = blockIdx.x * TM;
    const int o0 = blockIdx.y * TN;
    const int b  = blockIdx.z;

    if (tid == 0) {
        #pragma unroll
        for (int s = 0; s < NS; s++) {
            MBARRIER_INIT(sb + OFF_FULL + 8 * s, 1);        // tx-based
            MBARRIER_INIT(sb + OFF_EMPTY + 8 * s, NWARP_C); // 1 arrive per compute warp
        }
        FENCE_PROXY();
    }
    __syncthreads();

    if (wid == NWARP_C) {
        // ---------------- producer warp ----------------
        if (lane == 0) {
            int ps = 0, pp = 1;
            #pragma unroll 1
            for (int kc = 0; kc < NKC; kc++) {
                MBARRIER_WAIT_PARITY(sb + OFF_EMPTY + 8 * ps, pp);
                MBARRIER_EXPECT_TX(sb + OFF_FULL + 8 * ps, STAGE_BYTES);
                TMA_LOAD_3D(sb + OFF_A + ps * A_STAGE_BYTES, &tmx, kc * KC, b, l0, sb + OFF_FULL + 8 * ps);
                TMA_LOAD_3D(sb + OFF_B + ps * B_STAGE_BYTES, &tmw, kc * KC, o0, b, sb + OFF_FULL + 8 * ps);
                if (++ps == NS) { ps = 0; pp ^= 1; }
            }
        }
    } else {
        // ---------------- compute warps ----------------
        const int wm = wid & 1;        // 0..1 -> M offset
        const int wn = wid >> 1;       // 0..3 -> N offset
        const uint32_t rowA0 = (uint32_t)(wm * 64 + g) * 128;      // + i*2048 (+1024 for +8 rows)
        const uint32_t rowB0 = (uint32_t)(wn * 64 + g) * 128;      // + j*1024

        float acc[4][8][4];
        #pragma unroll
        for (int i = 0; i < 4; i++)
            #pragma unroll
            for (int j = 0; j < 8; j++)
                #pragma unroll
                for (int q = 0; q < 4; q++) acc[i][j][q] = 0.0f;

        int cs = 0, cp = 0;
        #pragma unroll 1
        for (int kc = 0; kc < NKC; kc++) {
            MBARRIER_WAIT_PARITY(sb + OFF_FULL + 8 * cs, cp);
            const uint32_t sA = sb + OFF_A + cs * A_STAGE_BYTES + rowA0;
            const uint32_t sB = sb + OFF_B + cs * B_STAGE_BYTES + rowB0;

            #pragma unroll
            for (int s = 0; s < 4; s++) {
                // SW128: byte col for chunk (2s) is 16*((2s)^g)+4t; next chunk flips bit4
                const uint32_t c0 = ((((uint32_t)(2 * s) ^ (uint32_t)g) << 4) | ((uint32_t)t << 2));
                const uint32_t c1 = c0 ^ 16u;

                uint32_t afr[4][4];
                #pragma unroll
                for (int i = 0; i < 4; i++) {
                    const uint32_t r0 = sA + (uint32_t)i * 2048u;
                    afr[i][0] = tf32_rna_u32(lds_u32(r0 + c0));          // row g,   col t
                    afr[i][1] = tf32_rna_u32(lds_u32(r0 + 1024u + c0));  // row g+8, col t
                    afr[i][2] = tf32_rna_u32(lds_u32(r0 + c1));          // row g,   col t+4
                    afr[i][3] = tf32_rna_u32(lds_u32(r0 + 1024u + c1));  // row g+8, col t+4
                }
                uint32_t bfr[8][2];
                #pragma unroll
                for (int j = 0; j < 8; j++) {
                    const uint32_t rb = sB + (uint32_t)j * 1024u;
                    bfr[j][0] = lds_u32(rb + c0);   // k=t,   n=g   (pre-rounded in wagg)
                    bfr[j][1] = lds_u32(rb + c1);   // k=t+4, n=g
                }
                #pragma unroll
                for (int i = 0; i < 4; i++)
                    #pragma unroll
                    for (int j = 0; j < 8; j++)
                        mma_tf32(acc[i][j], afr[i], bfr[j]);
            }

            __syncwarp();
            if (lane == 0) MBARRIER_ARRIVE(sb + OFF_EMPTY + 8 * cs);
            if (++cs == NS) { cs = 0; cp ^= 1; }
        }

        // ---------------- epilogue: registers -> gmem with bias ----------------
        const int colbase = o0 + wn * 64 + 2 * t;
        float2 bv[8];
        #pragma unroll
        for (int j = 0; j < 8; j++)
            bv[j] = *reinterpret_cast<const float2*>(bb + b * COUT + colbase + j * 8);

        #pragma unroll
        for (int i = 0; i < 4; i++) {
            #pragma unroll
            for (int p = 0; p < 2; p++) {
                const int l = l0 + wm * 64 + i * 16 + g + 8 * p;
                float* orow = out + ((size_t)l * B_DIM + b) * COUT + colbase;
                #pragma unroll
                for (int j = 0; j < 8; j++) {
                    float2 v;
                    v.x = acc[i][j][2 * p]     + bv[j].x;
                    v.y = acc[i][j][2 * p + 1] + bv[j].y;
                    *reinterpret_cast<float2*>(orow + j * 8) = v;
                }
            }
        }
    }

    __syncthreads();
    if (tid == 0) {
        #pragma unroll
        for (int s = 0; s < NS; s++) {
            MBAR_INVAL(sb + OFF_FULL + 8 * s);
            MBAR_INVAL(sb + OFF_EMPTY + 8 * s);
        }
    }
}

// ============================ fallback: SIMT fp32 GEMM (no TMA/tensor maps) ============================
__global__ void __launch_bounds__(256, 2)
gemm_fallback_kernel(const float* __restrict__ x, const float* __restrict__ bb,
                     float* __restrict__ out, int enabled) {
    if (!enabled) return;
    __shared__ float sx[64][33];     // 64 rows x 32 k (padded)
    const int l0 = blockIdx.x * 64;
    const int o0 = blockIdx.y * 128;
    const int b  = blockIdx.z;
    const int tid = threadIdx.x;
    const int tr = tid >> 5;         // 0..7 row group
    const int tc = tid & 31;

    float acc[8][4];
    #pragma unroll
    for (int i = 0; i < 8; i++)
        #pragma unroll
        for (int j = 0; j < 4; j++) acc[i][j] = 0.0f;

    for (int k0 = 0; k0 < CIN; k0 += 32) {
        __syncthreads();
        #pragma unroll
        for (int i = 0; i < 8; i++) {
            const int row = tr + i * 8;
            sx[row][tc] = x[((size_t)(l0 + row) * B_DIM + b) * CIN + k0 + tc];
        }
        __syncthreads();
        #pragma unroll 4
        for (int kk = 0; kk < 32; kk++) {
            float wv[4];
            #pragma unroll
            for (int j = 0; j < 4; j++)
                wv[j] = g_w[((size_t)b * COUT + o0 + tc + 32 * j) * CIN + k0 + kk];
            #pragma unroll
            for (int i = 0; i < 8; i++) {
                const float xv = sx[tr + i * 8][kk];
                #pragma unroll
                for (int j = 0; j < 4; j++) acc[i][j] = fmaf(xv, wv[j], acc[i][j]);
            }
        }
    }
    #pragma unroll
    for (int i = 0; i < 8; i++) {
        const int l = l0 + tr + i * 8;
        #pragma unroll
        for (int j = 0; j < 4; j++) {
            const int o = o0 + tc + 32 * j;
            out[((size_t)l * B_DIM + b) * COUT + o] = acc[i][j] + bb[b * COUT + o];
        }
    }
}

// ============================ host launch ============================
typedef CUresult (CUDAAPI *EncodeTiledFn)(
    CUtensorMap*, CUtensorMapDataType, cuuint32_t, void*,
    const cuuint64_t*, const cuuint64_t*, const cuuint32_t*, const cuuint32_t*,
    CUtensorMapInterleave, CUtensorMapSwizzle, CUtensorMapL2promotion, CUtensorMapFloatOOBfill);

extern "C" void kernel_launch(void* const* d_in, const int* in_sizes, int n_in,
                              void* d_out, int out_size) {
    const float* x      = (const float*)d_in[0];
    const float* cond   = (const float*)d_in[1];
    const float* fc1w   = (const float*)d_in[2];
    const float* fc1b   = (const float*)d_in[3];
    const float* fc2w   = (const float*)d_in[4];
    const float* fc2b   = (const float*)d_in[5];
    const float* weight = (const float*)d_in[6];
    const float* bias   = (const float*)d_in[7];
    float* out = (float*)d_out;

    void *p_w = nullptr, *p_bb = nullptr;
    cudaGetSymbolAddress(&p_w, g_w);
    cudaGetSymbolAddress(&p_bb, g_bb);

    // Resolve cuTensorMapEncodeTiled defensively; fall back to SIMT path on ANY failure.
    EncodeTiledFn enc = nullptr;
    {
        cudaDriverEntryPointQueryResult qres = cudaDriverEntryPointSymbolNotFound;
        cudaError_t e = cudaGetDriverEntryPointByVersion(
            "cuTensorMapEncodeTiled", (void**)&enc, 12000, cudaEnableDefault, &qres);
        if (e != cudaSuccess || qres != cudaDriverEntryPointSuccess) enc = nullptr;
        if (!enc) {
            qres = cudaDriverEntryPointSymbolNotFound;
            e = cudaGetDriverEntryPoint("cuTensorMapEncodeTiled", (void**)&enc,
                                        cudaEnableDefault, &qres);
            if (e != cudaSuccess || qres != cudaDriverEntryPointSuccess) enc = nullptr;
        }
    }

    CUtensorMap tmx, tmw;
    bool fast = (enc != nullptr);
    if (fast) {
        // x: logical dims (CIN, B, L), box (KC, 1, TM), SW128
        cuuint64_t dimsx[3]    = {CIN, B_DIM, L_DIM};
        cuuint64_t stridesx[2] = {(cuuint64_t)CIN * 4, (cuuint64_t)CIN * B_DIM * 4};
        cuuint32_t boxx[3]     = {KC, 1, TM};
        cuuint32_t es[3]       = {1, 1, 1};
        if (enc(&tmx, CU_TENSOR_MAP_DATA_TYPE_FLOAT32, 3, (void*)x, dimsx, stridesx, boxx, es,
                CU_TENSOR_MAP_INTERLEAVE_NONE, CU_TENSOR_MAP_SWIZZLE_128B,
                CU_TENSOR_MAP_L2_PROMOTION_L2_128B, CU_TENSOR_MAP_FLOAT_OOB_FILL_NONE)
            != CUDA_SUCCESS) fast = false;
        // w_agg: logical dims (CIN, COUT, B), box (KC, TN, 1), SW128
        cuuint64_t dimsw[3]    = {CIN, COUT, B_DIM};
        cuuint64_t stridesw[2] = {(cuuint64_t)CIN * 4, (cuuint64_t)CIN * COUT * 4};
        cuuint32_t boxw[3]     = {KC, TN, 1};
        if (fast &&
            enc(&tmw, CU_TENSOR_MAP_DATA_TYPE_FLOAT32, 3, p_w, dimsw, stridesw, boxw, es,
                CU_TENSOR_MAP_INTERLEAVE_NONE, CU_TENSOR_MAP_SWIZZLE_128B,
                CU_TENSOR_MAP_L2_PROMOTION_L2_128B, CU_TENSOR_MAP_FLOAT_OOB_FILL_NONE)
            != CUDA_SUCCESS) fast = false;
    }
    if (!fast) {
        memset(&tmx, 0, sizeof(tmx));
        memset(&tmw, 0, sizeof(tmw));
    }

    attn_kernel<<<1, 512>>>(cond, fc1w, fc1b, fc2w, fc2b, bias);
    wagg_kernel<<<(COUT * CIN / 4) / 256, 256>>>(weight);

    if (fast) {
        cudaFuncSetAttribute(gemm_tf32_kernel, cudaFuncAttributeMaxDynamicSharedMemorySize, SMEM_TOTAL);
        gemm_tf32_kernel<<<dim3(L_DIM / TM, COUT / TN, B_DIM), NTHREADS, SMEM_TOTAL>>>(
            tmx, tmw, (const float*)p_bb, out, 1);
    } else {
        gemm_fallback_kernel<<<dim3(L_DIM / 64, COUT / 128, B_DIM), 256>>>(
            x, (const float*)p_bb, out, 1);
    }
}

// round 6
// speedup vs baseline: 1.6436x; 1.2213x over previous
#include <cuda_runtime.h>
#include <cuda.h>
#include <cstdint>
#include <math.h>

// ============================ problem constants ============================
#define L_DIM  1024
#define B_DIM  8
#define CIN    1024
#define COUT   1024
#define KEXP   4
#define CCOND  256
#define HIDD   64

// ============================ GEMM tiling ============================
#define TM   128            // M tile (L dimension)
#define TN   128            // N tile (C_OUT dimension)
#define KC   32             // K floats per stage (128B row = SW128 atom)
#define NKC  (CIN / KC)     // 32 K-chunks
#define NS   3              // pipeline stages
#define NWARP_C 8           // compute warps
#define NTHREADS (NWARP_C * 32 + 32)   // + 1 producer warp = 288

#define A_STAGE_BYTES (TM * KC * 4)          // 16384
#define B_STAGE_BYTES (TN * KC * 4)          // 16384
#define STAGE_BYTES   (A_STAGE_BYTES + B_STAGE_BYTES)

#define OFF_FULL   0u
#define OFF_EMPTY  (8u * NS)
#define OFF_A      1024u
#define OFF_B      (1024u + NS * A_STAGE_BYTES)                // 50176 (1024-aligned)
#define SMEM_TOTAL ((int)(OFF_B + NS * B_STAGE_BYTES))         // 99328 -> 2 CTAs/SM

// ============================ scratch (device globals; no allocs) ============================
__device__ __align__(256) float g_w[(size_t)B_DIM * COUT * CIN];   // 32 MB aggregated + tf32-RNA weights
__device__ __align__(16)  float g_bb[B_DIM * COUT];                // aggregated bias
__device__ __align__(16)  float g_att[B_DIM * KEXP];               // softmax attention

// ============================ PTX helpers (sm_100 BASELINE only) ============================
__device__ __forceinline__ uint32_t smem_u32(const void* p) {
    uint32_t a;
    asm("{ .reg .u64 t; cvta.to.shared.u64 t, %1; cvt.u32.u64 %0, t; }" : "=r"(a) : "l"(p));
    return a;
}

#define MBARRIER_INIT(addr, cnt) \
    asm volatile("mbarrier.init.shared.b64 [%0], %1;" :: "r"(addr), "r"((uint32_t)(cnt)) : "memory")

#define MBARRIER_EXPECT_TX(addr, bytes) \
    asm volatile("mbarrier.arrive.expect_tx.shared.b64 _, [%0], %1;" :: "r"(addr), "r"((uint32_t)(bytes)) : "memory")

#define MBARRIER_ARRIVE(addr) \
    asm volatile("mbarrier.arrive.shared.b64 _, [%0];" :: "r"(addr) : "memory")

#define MBAR_INVAL(addr) \
    asm volatile("mbarrier.inval.shared.b64 [%0];" :: "r"(addr) : "memory")

#define MBARRIER_WAIT_PARITY(mbar_smem_addr, phase_parity) do {                          \
    uint32_t _mbar = (uint32_t)(mbar_smem_addr);                                         \
    uint32_t _parity = (uint32_t)(phase_parity);                                         \
    uint32_t _done;                                                                      \
    asm volatile(                                                                        \
        "{\n\t"                                                                          \
        ".reg .pred p;\n\t"                                                              \
        "mbarrier.try_wait.parity.acquire.cta.shared::cta.b64 p, [%1], %2;\n\t"          \
        "selp.b32 %0, 1, 0, p;\n\t"                                                      \
        "}"                                                                              \
        : "=r"(_done) : "r"(_mbar), "r"(_parity) : "memory");                            \
    if (!_done) {                                                                        \
        asm volatile(                                                                    \
            "{\n\t"                                                                      \
            ".reg .pred P1;\n\t"                                                         \
            "WAIT_LOOP_%=:\n\t"                                                          \
            "mbarrier.try_wait.parity.acquire.cta.shared::cta.b64 P1, [%0], %1, 0x989680;\n\t" \
            "@P1 bra.uni WAIT_DONE_%=;\n\t"                                              \
            "bra.uni WAIT_LOOP_%=;\n\t"                                                  \
            "WAIT_DONE_%=:\n\t"                                                          \
            "}"                                                                          \
            :: "r"(_mbar), "r"(_parity) : "memory");                                     \
    }                                                                                    \
} while (0)

#define TMA_LOAD_3D(smem_addr, tensor_map, cx, cy, cz, mbar) \
    asm volatile( \
        "cp.async.bulk.tensor.3d.shared::cta.global.tile.mbarrier::complete_tx::bytes " \
        "[%0], [%1, {%2, %3, %4}], [%5];" \
        :: "r"((uint32_t)(smem_addr)), "l"(tensor_map), \
           "r"((int32_t)(cx)), "r"((int32_t)(cy)), "r"((int32_t)(cz)), \
           "r"((uint32_t)(mbar)) \
        : "memory")

#define FENCE_PROXY() \
    asm volatile("fence.proxy.async.shared::cta;" ::: "memory")

__device__ __forceinline__ uint32_t lds_u32(uint32_t addr) {
    uint32_t v;
    asm volatile("ld.shared.b32 %0, [%1];" : "=r"(v) : "r"(addr));
    return v;
}

// tf32 round-to-nearest (ties away): add half-ulp at bit 13, mask. Carry into
// the exponent is correct rounding. Inputs are finite, so no NaN/Inf handling.
__device__ __forceinline__ uint32_t tf32_rna_u32(uint32_t u) {
    return (u + 0x1000u) & 0xFFFFE000u;
}
__device__ __forceinline__ float tf32_round(float v) {
    return __uint_as_float(tf32_rna_u32(__float_as_uint(v)));
}

// mma.sync m16n8k8 tf32 (sm_80+ baseline)
__device__ __forceinline__ void mma_tf32(float* d, const uint32_t* a, const uint32_t* b) {
    asm volatile(
        "mma.sync.aligned.m16n8k8.row.col.f32.tf32.tf32.f32 "
        "{%0,%1,%2,%3}, {%4,%5,%6,%7}, {%8,%9}, {%0,%1,%2,%3};"
        : "+f"(d[0]), "+f"(d[1]), "+f"(d[2]), "+f"(d[3])
        : "r"(a[0]), "r"(a[1]), "r"(a[2]), "r"(a[3]), "r"(b[0]), "r"(b[1]));
}

// ============================ kernel 1: attention + aggregated bias ============================
// fc1w staged in smem via bulk coalesced loads; one h-output per thread from smem.
#define FC1_PAD 257
#define ATTN_SMEM ((B_DIM * CCOND + HIDD * FC1_PAD) * 4)   // 8KB cond + ~64KB fc1w
__global__ void attn_kernel(const float* __restrict__ cond,
                            const float* __restrict__ fc1w, const float* __restrict__ fc1b,
                            const float* __restrict__ fc2w, const float* __restrict__ fc2b,
                            const float* __restrict__ bias) {
    extern __shared__ float dyn[];
    float* sc = dyn;                         // [B_DIM][CCOND]
    float* sw = dyn + B_DIM * CCOND;         // [HIDD][FC1_PAD]
    __shared__ float h[B_DIM][HIDD];
    __shared__ float lo[B_DIM][KEXP];
    __shared__ float att[B_DIM][KEXP];
    const int t = threadIdx.x;   // 512 threads

    // stage cond (8 KB) and fc1w (64 KB) with coalesced float4 loads, high MLP
    {
        const float4* c4 = reinterpret_cast<const float4*>(cond);
        #pragma unroll
        for (int i = t; i < B_DIM * CCOND / 4; i += 512) {
            float4 v = c4[i];
            sc[4 * i + 0] = v.x; sc[4 * i + 1] = v.y; sc[4 * i + 2] = v.z; sc[4 * i + 3] = v.w;
        }
        const float4* w4 = reinterpret_cast<const float4*>(fc1w);
        #pragma unroll
        for (int i = t; i < HIDD * CCOND / 4; i += 512) {
            float4 v = w4[i];
            const int e = 4 * i;                   // element index in row-major [HIDD][CCOND]
            const int j = e >> 8, k = e & 255;     // row, col
            float* dst = sw + j * FC1_PAD + k;
            dst[0] = v.x; dst[1] = v.y; dst[2] = v.z; dst[3] = v.w;
        }
    }
    __syncthreads();

    // h = relu(cond @ fc1_w^T + fc1_b): thread t -> (b = t>>6, j = t&63), dot from smem
    {
        const int b = t >> 6, j = t & 63;
        const float* cb = sc + b * CCOND;
        const float* wj = sw + j * FC1_PAD;
        float s = 0.0f;
        #pragma unroll 16
        for (int i = 0; i < CCOND; i++) s = fmaf(cb[i], wj[i], s);
        h[b][j] = fmaxf(s + fc1b[j], 0.0f);
    }
    __syncthreads();

    // logits = (h @ fc2_w^T + fc2_b) / TEMP   (8 x 4)
    if (t < B_DIM * KEXP) {
        const int b = t >> 2, k = t & 3;
        const float* wv = fc2w + k * HIDD;
        float acc = fc2b[k];
        #pragma unroll 8
        for (int i = 0; i < HIDD; i++) acc = fmaf(h[b][i], wv[i], acc);
        lo[b][k] = acc * (1.0f / 30.0f);
    }
    __syncthreads();

    // softmax over K=4
    if (t < B_DIM) {
        float m = fmaxf(fmaxf(lo[t][0], lo[t][1]), fmaxf(lo[t][2], lo[t][3]));
        float e[KEXP], s = 0.0f;
        #pragma unroll
        for (int k = 0; k < KEXP; k++) { e[k] = expf(lo[t][k] - m); s += e[k]; }
        float inv = 1.0f / s;
        #pragma unroll
        for (int k = 0; k < KEXP; k++) { att[t][k] = e[k] * inv; g_att[t * KEXP + k] = e[k] * inv; }
    }
    __syncthreads();

    // b_b = att @ bias   (8 x 1024), coalesced over o
    for (int idx = t; idx < B_DIM * COUT; idx += 512) {
        const int b = idx >> 10, o = idx & 1023;
        float acc = 0.0f;
        #pragma unroll
        for (int k = 0; k < KEXP; k++) acc = fmaf(att[b][k], bias[k * COUT + o], acc);
        g_bb[idx] = acc;
    }
}

// ============================ kernel 2: per-sample weight aggregation (+ tf32-RNA round) ============================
__global__ void wagg_kernel(const float* __restrict__ weight) {
    __shared__ float a[B_DIM * KEXP];
    if (threadIdx.x < B_DIM * KEXP) a[threadIdx.x] = g_att[threadIdx.x];
    __syncthreads();

    const int t = blockIdx.x * blockDim.x + threadIdx.x;   // over COUT*CIN/4 float4s
    const float4* w4 = reinterpret_cast<const float4*>(weight);
    float4 wk[KEXP];
    #pragma unroll
    for (int k = 0; k < KEXP; k++) wk[k] = w4[k * (COUT * CIN / 4) + t];

    float4* g4 = reinterpret_cast<float4*>(g_w);
    #pragma unroll
    for (int b = 0; b < B_DIM; b++) {
        float4 acc = make_float4(0.f, 0.f, 0.f, 0.f);
        #pragma unroll
        for (int k = 0; k < KEXP; k++) {
            const float ab = a[b * KEXP + k];
            acc.x = fmaf(ab, wk[k].x, acc.x);
            acc.y = fmaf(ab, wk[k].y, acc.y);
            acc.z = fmaf(ab, wk[k].z, acc.z);
            acc.w = fmaf(ab, wk[k].w, acc.w);
        }
        acc.x = tf32_round(acc.x); acc.y = tf32_round(acc.y);
        acc.z = tf32_round(acc.z); acc.w = tf32_round(acc.w);
        g4[b * (COUT * CIN / 4) + t] = acc;
    }
}

// ============================ kernel 3: tf32 mma.sync batched GEMM ============================
// CTA tile 128x128, 2 CTAs/SM. 8 compute warps (4Mx2N, warp tile 32x64) + producer warp.
__global__ void __launch_bounds__(NTHREADS, 2)
gemm_tf32_kernel(const __grid_constant__ CUtensorMap tmx,
                 const __grid_constant__ CUtensorMap tmw,
                 const float* __restrict__ bb,
                 float* __restrict__ out,
                 int enabled) {
    if (!enabled) return;     // fallback path active: SIMT kernel does the work
    extern __shared__ char smem[];
    const uint32_t sb = smem_u32(smem);
    const int tid  = threadIdx.x;
    const int wid  = tid >> 5;
    const int lane = tid & 31;
    const int g = lane >> 2;      // group id (0..7)
    const int t = lane & 3;       // thread-in-group (0..3)
    const int l0 = blockIdx.x * TM;
    const int o0 = blockIdx.y * TN;
    const int b  = blockIdx.z;

    if (tid == 0) {
        #pragma unroll
        for (int s = 0; s < NS; s++) {
            MBARRIER_INIT(sb + OFF_FULL + 8 * s, 1);        // tx-based
            MBARRIER_INIT(sb + OFF_EMPTY + 8 * s, NWARP_C); // 1 arrive per compute warp
        }
        FENCE_PROXY();
    }
    __syncthreads();

    if (wid == NWARP_C) {
        // ---------------- producer warp ----------------
        if (lane == 0) {
            int ps = 0, pp = 1;
            #pragma unroll 1
            for (int kc = 0; kc < NKC; kc++) {
                MBARRIER_WAIT_PARITY(sb + OFF_EMPTY + 8 * ps, pp);
                MBARRIER_EXPECT_TX(sb + OFF_FULL + 8 * ps, STAGE_BYTES);
                TMA_LOAD_3D(sb + OFF_A + ps * A_STAGE_BYTES, &tmx, kc * KC, b, l0, sb + OFF_FULL + 8 * ps);
                TMA_LOAD_3D(sb + OFF_B + ps * B_STAGE_BYTES, &tmw, kc * KC, o0, b, sb + OFF_FULL + 8 * ps);
                if (++ps == NS) { ps = 0; pp ^= 1; }
            }
        }
    } else {
        // ---------------- compute warps ----------------
        const int wm = wid & 3;        // 0..3 -> M offset (32 rows each)
        const int wn = wid >> 2;       // 0..1 -> N offset (64 cols each)
        const uint32_t rowA0 = (uint32_t)(wm * 32 + g) * 128;      // + i*2048 (+1024 for +8 rows)
        const uint32_t rowB0 = (uint32_t)(wn * 64 + g) * 128;      // + j*1024

        float acc[2][8][4];
        #pragma unroll
        for (int i = 0; i < 2; i++)
            #pragma unroll
            for (int j = 0; j < 8; j++)
                #pragma unroll
                for (int q = 0; q < 4; q++) acc[i][j][q] = 0.0f;

        int cs = 0, cp = 0;
        #pragma unroll 1
        for (int kc = 0; kc < NKC; kc++) {
            MBARRIER_WAIT_PARITY(sb + OFF_FULL + 8 * cs, cp);
            const uint32_t sA = sb + OFF_A + cs * A_STAGE_BYTES + rowA0;
            const uint32_t sB = sb + OFF_B + cs * B_STAGE_BYTES + rowB0;

            #pragma unroll
            for (int s = 0; s < 4; s++) {
                // SW128: byte col for chunk (2s) is 16*((2s)^g)+4t; next chunk flips bit4
                const uint32_t c0 = ((((uint32_t)(2 * s) ^ (uint32_t)g) << 4) | ((uint32_t)t << 2));
                const uint32_t c1 = c0 ^ 16u;

                uint32_t afr[2][4];
                #pragma unroll
                for (int i = 0; i < 2; i++) {
                    const uint32_t r0 = sA + (uint32_t)i * 2048u;
                    afr[i][0] = tf32_rna_u32(lds_u32(r0 + c0));          // row g,   col t
                    afr[i][1] = tf32_rna_u32(lds_u32(r0 + 1024u + c0));  // row g+8, col t
                    afr[i][2] = tf32_rna_u32(lds_u32(r0 + c1));          // row g,   col t+4
                    afr[i][3] = tf32_rna_u32(lds_u32(r0 + 1024u + c1));  // row g+8, col t+4
                }
                uint32_t bfr[8][2];
                #pragma unroll
                for (int j = 0; j < 8; j++) {
                    const uint32_t rb = sB + (uint32_t)j * 1024u;
                    bfr[j][0] = lds_u32(rb + c0);   // k=t,   n=g   (pre-rounded in wagg)
                    bfr[j][1] = lds_u32(rb + c1);   // k=t+4, n=g
                }
                #pragma unroll
                for (int i = 0; i < 2; i++)
                    #pragma unroll
                    for (int j = 0; j < 8; j++)
                        mma_tf32(acc[i][j], afr[i], bfr[j]);
            }

            __syncwarp();
            if (lane == 0) MBARRIER_ARRIVE(sb + OFF_EMPTY + 8 * cs);
            if (++cs == NS) { cs = 0; cp ^= 1; }
        }

        // ---------------- epilogue: registers -> gmem with bias ----------------
        const int colbase = o0 + wn * 64 + 2 * t;
        float2 bv[8];
        #pragma unroll
        for (int j = 0; j < 8; j++)
            bv[j] = *reinterpret_cast<const float2*>(bb + b * COUT + colbase + j * 8);

        #pragma unroll
        for (int i = 0; i < 2; i++) {
            #pragma unroll
            for (int p = 0; p < 2; p++) {
                const int l = l0 + wm * 32 + i * 16 + g + 8 * p;
                float* orow = out + ((size_t)l * B_DIM + b) * COUT + colbase;
                #pragma unroll
                for (int j = 0; j < 8; j++) {
                    float2 v;
                    v.x = acc[i][j][2 * p]     + bv[j].x;
                    v.y = acc[i][j][2 * p + 1] + bv[j].y;
                    *reinterpret_cast<float2*>(orow + j * 8) = v;
                }
            }
        }
    }

    __syncthreads();
    if (tid == 0) {
        #pragma unroll
        for (int s = 0; s < NS; s++) {
            MBAR_INVAL(sb + OFF_FULL + 8 * s);
            MBAR_INVAL(sb + OFF_EMPTY + 8 * s);
        }
    }
}

// ============================ fallback: SIMT fp32 GEMM (no TMA/tensor maps) ============================
__global__ void __launch_bounds__(256, 2)
gemm_fallback_kernel(const float* __restrict__ x, const float* __restrict__ bb,
                     float* __restrict__ out, int enabled) {
    if (!enabled) return;
    __shared__ float sx[64][33];     // 64 rows x 32 k (padded)
    const int l0 = blockIdx.x * 64;
    const int o0 = blockIdx.y * 128;
    const int b  = blockIdx.z;
    const int tid = threadIdx.x;
    const int tr = tid >> 5;         // 0..7 row group
    const int tc = tid & 31;

    float acc[8][4];
    #pragma unroll
    for (int i = 0; i < 8; i++)
        #pragma unroll
        for (int j = 0; j < 4; j++) acc[i][j] = 0.0f;

    for (int k0 = 0; k0 < CIN; k0 += 32) {
        __syncthreads();
        #pragma unroll
        for (int i = 0; i < 8; i++) {
            const int row = tr + i * 8;
            sx[row][tc] = x[((size_t)(l0 + row) * B_DIM + b) * CIN + k0 + tc];
        }
        __syncthreads();
        #pragma unroll 4
        for (int kk = 0; kk < 32; kk++) {
            float wv[4];
            #pragma unroll
            for (int j = 0; j < 4; j++)
                wv[j] = g_w[((size_t)b * COUT + o0 + tc + 32 * j) * CIN + k0 + kk];
            #pragma unroll
            for (int i = 0; i < 8; i++) {
                const float xv = sx[tr + i * 8][kk];
                #pragma unroll
                for (int j = 0; j < 4; j++) acc[i][j] = fmaf(xv, wv[j], acc[i][j]);
            }
        }
    }
    #pragma unroll
    for (int i = 0; i < 8; i++) {
        const int l = l0 + tr + i * 8;
        #pragma unroll
        for (int j = 0; j < 4; j++) {
            const int o = o0 + tc + 32 * j;
            out[((size_t)l * B_DIM + b) * COUT + o] = acc[i][j] + bb[b * COUT + o];
        }
    }
}

// ============================ host launch ============================
typedef CUresult (CUDAAPI *EncodeTiledFn)(
    CUtensorMap*, CUtensorMapDataType, cuuint32_t, void*,
    const cuuint64_t*, const cuuint64_t*, const cuuint32_t*, const cuuint32_t*,
    CUtensorMapInterleave, CUtensorMapSwizzle, CUtensorMapL2promotion, CUtensorMapFloatOOBfill);

extern "C" void kernel_launch(void* const* d_in, const int* in_sizes, int n_in,
                              void* d_out, int out_size) {
    const float* x      = (const float*)d_in[0];
    const float* cond   = (const float*)d_in[1];
    const float* fc1w   = (const float*)d_in[2];
    const float* fc1b   = (const float*)d_in[3];
    const float* fc2w   = (const float*)d_in[4];
    const float* fc2b   = (const float*)d_in[5];
    const float* weight = (const float*)d_in[6];
    const float* bias   = (const float*)d_in[7];
    float* out = (float*)d_out;

    void *p_w = nullptr, *p_bb = nullptr;
    cudaGetSymbolAddress(&p_w, g_w);
    cudaGetSymbolAddress(&p_bb, g_bb);

    // Resolve cuTensorMapEncodeTiled defensively; fall back to SIMT path on ANY failure.
    EncodeTiledFn enc = nullptr;
    {
        cudaDriverEntryPointQueryResult qres = cudaDriverEntryPointSymbolNotFound;
        cudaError_t e = cudaGetDriverEntryPointByVersion(
            "cuTensorMapEncodeTiled", (void**)&enc, 12000, cudaEnableDefault, &qres);
        if (e != cudaSuccess || qres != cudaDriverEntryPointSuccess) enc = nullptr;
        if (!enc) {
            qres = cudaDriverEntryPointSymbolNotFound;
            e = cudaGetDriverEntryPoint("cuTensorMapEncodeTiled", (void**)&enc,
                                        cudaEnableDefault, &qres);
            if (e != cudaSuccess || qres != cudaDriverEntryPointSuccess) enc = nullptr;
        }
    }

    CUtensorMap tmx, tmw;
    bool fast = (enc != nullptr);
    if (fast) {
        // x: logical dims (CIN, B, L), box (KC, 1, TM), SW128
        cuuint64_t dimsx[3]    = {CIN, B_DIM, L_DIM};
        cuuint64_t stridesx[2] = {(cuuint64_t)CIN * 4, (cuuint64_t)CIN * B_DIM * 4};
        cuuint32_t boxx[3]     = {KC, 1, TM};
        cuuint32_t es[3]       = {1, 1, 1};
        if (enc(&tmx, CU_TENSOR_MAP_DATA_TYPE_FLOAT32, 3, (void*)x, dimsx, stridesx, boxx, es,
                CU_TENSOR_MAP_INTERLEAVE_NONE, CU_TENSOR_MAP_SWIZZLE_128B,
                CU_TENSOR_MAP_L2_PROMOTION_L2_128B, CU_TENSOR_MAP_FLOAT_OOB_FILL_NONE)
            != CUDA_SUCCESS) fast = false;
        // w_agg: logical dims (CIN, COUT, B), box (KC, TN, 1), SW128
        cuuint64_t dimsw[3]    = {CIN, COUT, B_DIM};
        cuuint64_t stridesw[2] = {(cuuint64_t)CIN * 4, (cuuint64_t)CIN * COUT * 4};
        cuuint32_t boxw[3]     = {KC, TN, 1};
        if (fast &&
            enc(&tmw, CU_TENSOR_MAP_DATA_TYPE_FLOAT32, 3, p_w, dimsw, stridesw, boxw, es,
                CU_TENSOR_MAP_INTERLEAVE_NONE, CU_TENSOR_MAP_SWIZZLE_128B,
                CU_TENSOR_MAP_L2_PROMOTION_L2_128B, CU_TENSOR_MAP_FLOAT_OOB_FILL_NONE)
            != CUDA_SUCCESS) fast = false;
    }
    if (!fast) {
        memset(&tmx, 0, sizeof(tmx));
        memset(&tmw, 0, sizeof(tmw));
    }

    cudaFuncSetAttribute(attn_kernel, cudaFuncAttributeMaxDynamicSharedMemorySize, ATTN_SMEM);
    attn_kernel<<<1, 512, ATTN_SMEM>>>(cond, fc1w, fc1b, fc2w, fc2b, bias);
    wagg_kernel<<<(COUT * CIN / 4) / 256, 256>>>(weight);

    if (fast) {
        cudaFuncSetAttribute(gemm_tf32_kernel, cudaFuncAttributeMaxDynamicSharedMemorySize, SMEM_TOTAL);
        gemm_tf32_kernel<<<dim3(L_DIM / TM, COUT / TN, B_DIM), NTHREADS, SMEM_TOTAL>>>(
            tmx, tmw, (const float*)p_bb, out, 1);
    } else {
        gemm_fallback_kernel<<<dim3(L_DIM / 64, COUT / 128, B_DIM), 256>>>(
            x, (const float*)p_bb, out, 1);
    }
}